// round 16
// baseline (speedup 1.0000x reference)
#include <cuda_runtime.h>
#include <cuda_fp16.h>
#include <math.h>
#include <stdint.h>

// Problem constants
#define BATCH 4
#define SEQ   2048
#define DMODEL 512
#define NHEADS 4
#define HDIM  128
#define DFF   2048
#define MROWS (BATCH*SEQ)   // 8192

// ---------------------------------------------------------------------------
// Static scratch (no allocation allowed)
// ---------------------------------------------------------------------------
__device__ float  g_x1  [MROWS * DMODEL];       // fp32 residual
__device__ __half g_qkvh [MROWS * 3 * DMODEL];  // half (attention input)
__device__ __half g_ln1h [MROWS * DMODEL];
__device__ __half g_attnh[MROWS * DMODEL];
__device__ __half g_ln2h [MROWS * DMODEL];
__device__ __half g_ff1h [MROWS * DFF];
// transposed half weights [N,K]
__device__ __half g_wqkvT[3 * DMODEL * DMODEL];
__device__ __half g_wprojT[DMODEL * DMODEL];
__device__ __half g_wff1T[DFF * DMODEL];
__device__ __half g_wff2T[DMODEL * DFF];

#define ATT_SCALE 0.08838834764831845f   // 1/sqrt(128)

// ---------------------------------------------------------------------------
// PTX helpers
// ---------------------------------------------------------------------------
__device__ __forceinline__ void mma_f16(float c[4], const uint32_t a[4], const uint32_t b[2]) {
    asm volatile(
        "mma.sync.aligned.m16n8k16.row.col.f32.f16.f16.f32 "
        "{%0,%1,%2,%3}, {%4,%5,%6,%7}, {%8,%9}, {%0,%1,%2,%3};"
        : "+f"(c[0]), "+f"(c[1]), "+f"(c[2]), "+f"(c[3])
        : "r"(a[0]), "r"(a[1]), "r"(a[2]), "r"(a[3]), "r"(b[0]), "r"(b[1]));
}

__device__ __forceinline__ void ldsm_x4(uint32_t& r0, uint32_t& r1, uint32_t& r2, uint32_t& r3,
                                        uint32_t addr) {
    asm volatile("ldmatrix.sync.aligned.m8n8.x4.shared.b16 {%0,%1,%2,%3}, [%4];"
                 : "=r"(r0), "=r"(r1), "=r"(r2), "=r"(r3) : "r"(addr));
}
__device__ __forceinline__ void ldsm_x4_trans(uint32_t& r0, uint32_t& r1, uint32_t& r2, uint32_t& r3,
                                              uint32_t addr) {
    asm volatile("ldmatrix.sync.aligned.m8n8.x4.trans.shared.b16 {%0,%1,%2,%3}, [%4];"
                 : "=r"(r0), "=r"(r1), "=r"(r2), "=r"(r3) : "r"(addr));
}

__device__ __forceinline__ void cp16(uint32_t smem_addr, const void* gmem) {
    asm volatile("cp.async.cg.shared.global [%0], [%1], 16;" :: "r"(smem_addr), "l"(gmem));
}
__device__ __forceinline__ void cp_commit() { asm volatile("cp.async.commit_group;"); }
template <int N>
__device__ __forceinline__ void cp_wait() { asm volatile("cp.async.wait_group %0;" :: "n"(N)); }
__device__ __forceinline__ uint32_t smem_u32(const void* p) {
    return (uint32_t)__cvta_generic_to_shared(p);
}

// ---------------------------------------------------------------------------
// LayerNorm core: one warp handles TWO rows. Block (32,8): 16 rows per block.
// ---------------------------------------------------------------------------
__device__ __forceinline__ void ln_2rows(const float* __restrict__ x,
                                         const float* __restrict__ g,
                                         const float* __restrict__ b,
                                         __half* __restrict__ out,
                                         int row0, int lane)
{
    const float4* xr0 = (const float4*)(x + (size_t)row0 * DMODEL);
    const float4* xr1 = (const float4*)(x + (size_t)(row0 + 1) * DMODEL);
    float4 v0[4], v1[4];
    float sa = 0.f, sa2 = 0.f, sb = 0.f, sb2 = 0.f;
    #pragma unroll
    for (int i = 0; i < 4; i++) {
        v0[i] = xr0[lane + i * 32];
        v1[i] = xr1[lane + i * 32];
    }
    #pragma unroll
    for (int i = 0; i < 4; i++) {
        sa  += v0[i].x + v0[i].y + v0[i].z + v0[i].w;
        sa2 += v0[i].x*v0[i].x + v0[i].y*v0[i].y + v0[i].z*v0[i].z + v0[i].w*v0[i].w;
        sb  += v1[i].x + v1[i].y + v1[i].z + v1[i].w;
        sb2 += v1[i].x*v1[i].x + v1[i].y*v1[i].y + v1[i].z*v1[i].z + v1[i].w*v1[i].w;
    }
    #pragma unroll
    for (int o = 16; o > 0; o >>= 1) {
        sa  += __shfl_xor_sync(0xffffffffu, sa,  o);
        sa2 += __shfl_xor_sync(0xffffffffu, sa2, o);
        sb  += __shfl_xor_sync(0xffffffffu, sb,  o);
        sb2 += __shfl_xor_sync(0xffffffffu, sb2, o);
    }
    float mua  = sa * (1.f / DMODEL);
    float vara = sa2 * (1.f / DMODEL) - mua * mua;
    float inva = rsqrtf(vara + 1e-5f);
    float mub  = sb * (1.f / DMODEL);
    float varb = sb2 * (1.f / DMODEL) - mub * mub;
    float invb = rsqrtf(varb + 1e-5f);

    __half2* o0 = (__half2*)(out + (size_t)row0 * DMODEL);
    __half2* o1 = (__half2*)(out + (size_t)(row0 + 1) * DMODEL);
    const float4* g4 = (const float4*)g;
    const float4* b4 = (const float4*)b;
    #pragma unroll
    for (int i = 0; i < 4; i++) {
        float4 gg = g4[lane + i * 32];
        float4 bb = b4[lane + i * 32];
        float a0 = (v0[i].x - mua) * inva * gg.x + bb.x;
        float a1 = (v0[i].y - mua) * inva * gg.y + bb.y;
        float a2 = (v0[i].z - mua) * inva * gg.z + bb.z;
        float a3 = (v0[i].w - mua) * inva * gg.w + bb.w;
        o0[(lane + i * 32) * 2 + 0] = __floats2half2_rn(a0, a1);
        o0[(lane + i * 32) * 2 + 1] = __floats2half2_rn(a2, a3);
        float c0 = (v1[i].x - mub) * invb * gg.x + bb.x;
        float c1 = (v1[i].y - mub) * invb * gg.y + bb.y;
        float c2 = (v1[i].z - mub) * invb * gg.z + bb.z;
        float c3 = (v1[i].w - mub) * invb * gg.w + bb.w;
        o1[(lane + i * 32) * 2 + 0] = __floats2half2_rn(c0, c1);
        o1[(lane + i * 32) * 2 + 1] = __floats2half2_rn(c2, c3);
    }
}

__global__ void ln_kernel_h(const float* __restrict__ x,
                            const float* __restrict__ g,
                            const float* __restrict__ b,
                            __half* __restrict__ out)
{
    int row0 = blockIdx.x * 16 + threadIdx.y * 2;
    ln_2rows(x, g, b, out, row0, threadIdx.x);
}

// ---------------------------------------------------------------------------
// Prep kernel: fused 4 weight transposes (+fp16 convert) AND ln1.
// ---------------------------------------------------------------------------
__global__ void prep_kernel(const float* __restrict__ w_qkv, const float* __restrict__ w_proj,
                            const float* __restrict__ w_ff1, const float* __restrict__ w_ff2,
                            __half* __restrict__ qkvT, __half* __restrict__ projT,
                            __half* __restrict__ ff1T, __half* __restrict__ ff2T,
                            const float* __restrict__ x, const float* __restrict__ ln1_g,
                            const float* __restrict__ ln1_b, __half* __restrict__ ln1h)
{
    __shared__ float t[32][33];
    int bid = blockIdx.x;
    if (bid >= 3072) {
        int row0 = (bid - 3072) * 16 + threadIdx.y * 2;
        ln_2rows(x, ln1_g, ln1_b, ln1h, row0, threadIdx.x);
        return;
    }

    const float* B; __half* BT; int K, N, bx, by;
    if (bid < 768)        { B = w_qkv;  BT = qkvT;  K = DMODEL; N = 3*DMODEL; bx = bid % 48; by = bid / 48; }
    else if (bid < 1024)  { B = w_proj; BT = projT; K = DMODEL; N = DMODEL;   bid -= 768;  bx = bid % 16; by = bid / 16; }
    else if (bid < 2048)  { B = w_ff1;  BT = ff1T;  K = DMODEL; N = DFF;      bid -= 1024; bx = bid % 64; by = bid / 64; }
    else                  { B = w_ff2;  BT = ff2T;  K = DFF;    N = DMODEL;   bid -= 2048; bx = bid % 16; by = bid / 16; }

    int xcol = bx * 32 + threadIdx.x;
    int y0 = by * 32;
    #pragma unroll
    for (int i = 0; i < 4; i++) {
        int y = y0 + threadIdx.y + i * 8;
        t[threadIdx.y + i * 8][threadIdx.x] = B[(size_t)y * N + xcol];
    }
    __syncthreads();
    int xo  = by * 32 + threadIdx.x;
    int yo0 = bx * 32;
    #pragma unroll
    for (int i = 0; i < 4; i++) {
        int yo = yo0 + threadIdx.y + i * 8;
        BT[(size_t)yo * K + xo] = __float2half_rn(t[threadIdx.x][threadIdx.y + i * 8]);
    }
}

// ---------------------------------------------------------------------------
// fp16 tensor-core GEMM (m16n8k16), BK=64 stages, 3-stage cp.async pipeline,
// ldmatrix frags. Block 128x128x64, 256 threads = 8 warps (4m x 2n).
// EPI: 0 = float out, 1 = GELU half out, 2 = +residual float out, 3 = half out
// ---------------------------------------------------------------------------
#define HS_STR 72                        // halves per row (64 + 8 pad)
#define HT_ELEMS (128 * HS_STR)          // 9216 halves per tile
#define HSTAGE_ELEMS (2 * HT_ELEMS)      // A + B
#define GEMMH_SMEM (3 * HSTAGE_ELEMS * 2)   // 110592 B

__device__ __forceinline__ void load_stage_h(
    uint32_t dstA, uint32_t dstB,
    const __half* Ab, const __half* BTb, int k0, int K, int tid)
{
    #pragma unroll
    for (int t = 0; t < 4; t++) {
        int idx = tid + t * 256;          // 0..1023
        int r = idx >> 3, q = idx & 7;
        cp16(dstA + r * (HS_STR*2) + q * 16, Ab  + (size_t)r * K + k0 + q * 8);
        cp16(dstB + r * (HS_STR*2) + q * 16, BTb + (size_t)r * K + k0 + q * 8);
    }
}

template <int EPI>
__global__ void __launch_bounds__(256, 2)
gemm_h(const __half* __restrict__ A, const __half* __restrict__ BT,
       const float* __restrict__ res, void* __restrict__ Cv,
       int M, int N, int K)
{
    extern __shared__ __half smh[];
    const uint32_t smb = smem_u32(smh);
    uint32_t aAddr[3], bAddr[3];
    #pragma unroll
    for (int s = 0; s < 3; s++) {
        aAddr[s] = smb + s * HSTAGE_ELEMS * 2;
        bAddr[s] = aAddr[s] + HT_ELEMS * 2;
    }

    const int tid  = threadIdx.x;
    const int lane = tid & 31;
    const int wid  = tid >> 5;
    const int wm   = wid >> 1;     // 0..3 (m, x32)
    const int wn   = wid & 1;      // 0..1 (n, x64)

    const int bx = blockIdx.x;
    const int by = blockIdx.y;

    const __half* Ab  = A  + (size_t)(by * 128) * K;
    const __half* BTb = BT + (size_t)(bx * 128) * K;

    float acc[2][8][4];
    #pragma unroll
    for (int mf = 0; mf < 2; mf++)
        #pragma unroll
        for (int nf = 0; nf < 8; nf++)
            #pragma unroll
            for (int r = 0; r < 4; r++) acc[mf][nf][r] = 0.f;

    const int a_row = (lane & 15);
    const int a_col = (lane >> 4) << 3;
    const int b_row = (lane & 7) + ((lane >> 4) << 3);
    const int b_col = (lane & 8) ? 8 : 0;

    const int nt = K >> 6;   // BK=64 chunks
    load_stage_h(aAddr[0], bAddr[0], Ab, BTb, 0, K, tid);
    cp_commit();
    if (nt > 1) {
        load_stage_h(aAddr[1], bAddr[1], Ab, BTb, 64, K, tid);
        cp_commit();
    }

    for (int kt = 0; kt < nt; kt++) {
        const int cur = kt % 3;
        if (kt + 1 < nt) cp_wait<1>(); else cp_wait<0>();
        __syncthreads();

        if (kt + 2 < nt) {
            const int nxt = (kt + 2) % 3;
            load_stage_h(aAddr[nxt], bAddr[nxt], Ab, BTb, (kt + 2) * 64, K, tid);
            cp_commit();
        }

        const uint32_t Asc = aAddr[cur];
        const uint32_t Bsc = bAddr[cur];

        #pragma unroll
        for (int ks = 0; ks < 4; ks++) {
            const int kb = ks * 16;
            uint32_t af[2][4], bf[8][2];
            #pragma unroll
            for (int mf = 0; mf < 2; mf++) {
                int r = wm * 32 + mf * 16 + a_row;
                ldsm_x4(af[mf][0], af[mf][1], af[mf][2], af[mf][3],
                        Asc + (r * HS_STR + kb + a_col) * 2);
            }
            #pragma unroll
            for (int p = 0; p < 4; p++) {
                int n = wn * 64 + p * 16 + b_row;
                ldsm_x4(bf[2*p][0], bf[2*p][1], bf[2*p+1][0], bf[2*p+1][1],
                        Bsc + (n * HS_STR + kb + b_col) * 2);
            }
            #pragma unroll
            for (int mf = 0; mf < 2; mf++)
                #pragma unroll
                for (int nf = 0; nf < 8; nf++)
                    mma_f16(acc[mf][nf], af[mf], bf[nf]);
        }
    }

    // epilogue
    const int g   = lane >> 2;
    const int tig = lane & 3;
    #pragma unroll
    for (int mf = 0; mf < 2; mf++) {
        #pragma unroll
        for (int i2 = 0; i2 < 2; i2++) {
            int row = by * 128 + wm * 32 + mf * 16 + g + i2 * 8;
            #pragma unroll
            for (int nf = 0; nf < 8; nf++) {
                int col = bx * 128 + wn * 64 + nf * 8 + tig * 2;
                float v0 = acc[mf][nf][i2 * 2 + 0];
                float v1 = acc[mf][nf][i2 * 2 + 1];
                size_t off = (size_t)row * N + col;
                if (EPI == 1) {
                    v0 = 0.5f * v0 * (1.f + erff(v0 * 0.70710678118654752f));
                    v1 = 0.5f * v1 * (1.f + erff(v1 * 0.70710678118654752f));
                    *(__half2*)((__half*)Cv + off) = __floats2half2_rn(v0, v1);
                } else if (EPI == 2) {
                    float2 r = *(const float2*)(res + off);
                    *(float2*)((float*)Cv + off) = make_float2(v0 + r.x, v1 + r.y);
                } else if (EPI == 3) {
                    *(__half2*)((__half*)Cv + off) = __floats2half2_rn(v0, v1);
                } else {
                    *(float2*)((float*)Cv + off) = make_float2(v0, v1);
                }
            }
        }
    }
}

// ---------------------------------------------------------------------------
// fp16 flash attention v5: BQ=64 (4 warps x 16 q-rows), register-resident P,
// 2-stage cp.async K/V pipeline, software-pipelined fragment loads.
// 512 CTAs heavy-first. Smem: Q[64][136] + 2 x (K+V)[64][136] = 87040 B.
// ---------------------------------------------------------------------------
#define BQA 64
#define BKA 64
#define QSTR 136   // halves
#define KSTR 136
#define VSTR 136
#define KV_STAGE_ELEMS (BKA * KSTR + BKA * VSTR)       // 17408 halves
#define ATTN_SMEM ((BQA*QSTR + 2*KV_STAGE_ELEMS) * 2)  // 87040 B

__global__ void __launch_bounds__(128, 2)
attn_h(const __half* __restrict__ qkv, __half* __restrict__ out)
{
    extern __shared__ __align__(16) __half smah[];
    __half* Qs = smah;                               // [64][136]
    uint32_t kAddr[2], vAddr[2];
    {
        uint32_t kv0 = smem_u32(Qs + BQA * QSTR);
        kAddr[0] = kv0;
        vAddr[0] = kv0 + BKA * KSTR * 2;
        kAddr[1] = kv0 + KV_STAGE_ELEMS * 2;
        vAddr[1] = kAddr[1] + BKA * KSTR * 2;
    }
    __half* KsBase = Qs + BQA * QSTR;
    const uint32_t qAddr = smem_u32(Qs);

    const int qblk = (SEQ / BQA - 1) - blockIdx.x;   // heavy blocks first
    const int h  = blockIdx.y;
    const int b  = blockIdx.z;
    const int tid  = threadIdx.x;
    const int lane = tid & 31;
    const int wid  = tid >> 5;
    const int g    = lane >> 2;
    const int tig  = lane & 3;
    const int m0w  = wid * 16;

    const size_t rstride = 3 * DMODEL;  // halves
    const float scale = ATT_SCALE;

    const int a_row = (lane & 15);
    const int a_col = (lane >> 4) << 3;
    const int b_row = (lane & 7) + ((lane >> 4) << 3);
    const int b_col = (lane & 8) ? 8 : 0;

    const __half* kvbase = qkv + (size_t)b * SEQ * rstride + h * HDIM + DMODEL;

    // ---- prologue: Q tile + K/V tile 0 via cp.async (one group) ----
    {
        const __half* qbase = qkv + ((size_t)b * SEQ + qblk * BQA) * rstride + h * HDIM;
        #pragma unroll
        for (int t = 0; t < 8; t++) {
            int idx = tid + t * 128;
            int row = idx >> 4, q8 = idx & 15;
            cp16(qAddr + (row * QSTR + q8 * 8) * 2, qbase + (size_t)row * rstride + q8 * 8);
        }
        #pragma unroll
        for (int t = 0; t < 8; t++) {
            int idx = tid + t * 128;
            int row = idx >> 4, q8 = idx & 15;
            cp16(kAddr[0] + (row * KSTR + q8 * 8) * 2, kvbase + (size_t)row * rstride + q8 * 8);
            cp16(vAddr[0] + (row * VSTR + q8 * 8) * 2, kvbase + DMODEL + (size_t)row * rstride + q8 * 8);
        }
        cp_commit();
    }

    float o[16][4];
    #pragma unroll
    for (int nf = 0; nf < 16; nf++)
        #pragma unroll
        for (int r = 0; r < 4; r++) o[nf][r] = 0.f;
    float m0 = -1e30f, m1 = -1e30f, l0 = 0.f, l1 = 0.f;

    const int ntiles = qblk + 1;

    for (int kt = 0; kt < ntiles; kt++) {
        const int cur = kt & 1;
        __syncthreads();

        if (kt + 1 < ntiles) {
            const int nxt = 1 - cur;
            const __half* kbn = kvbase + (size_t)(kt + 1) * BKA * rstride;
            #pragma unroll
            for (int t = 0; t < 8; t++) {
                int idx = tid + t * 128;
                int row = idx >> 4, q8 = idx & 15;
                cp16(kAddr[nxt] + (row * KSTR + q8 * 8) * 2, kbn + (size_t)row * rstride + q8 * 8);
                cp16(vAddr[nxt] + (row * VSTR + q8 * 8) * 2, kbn + DMODEL + (size_t)row * rstride + q8 * 8);
            }
            cp_commit();
            cp_wait<1>();
        } else {
            cp_wait<0>();
        }
        __syncthreads();

        const __half* Ks = KsBase + cur * KV_STAGE_ELEMS;
        const __half* Vs = Ks + BKA * KSTR;

        // ---- S = Q K^T  (software-pipelined fragment loads) ----
        float s[8][4];
        #pragma unroll
        for (int nf = 0; nf < 8; nf++)
            #pragma unroll
            for (int r = 0; r < 4; r++) s[nf][r] = 0.f;

        uint32_t aC[4], bC[8][2], aN[4], bN[8][2];
        // preload kb8 = 0
        ldsm_x4(aC[0], aC[1], aC[2], aC[3],
                smem_u32(&Qs[(m0w + a_row) * QSTR + a_col]));
        #pragma unroll
        for (int p = 0; p < 4; p++) {
            int n = p * 16 + b_row;
            ldsm_x4(bC[2*p][0], bC[2*p][1], bC[2*p+1][0], bC[2*p+1][1],
                    smem_u32(&Ks[n * KSTR + b_col]));
        }
        #pragma unroll
        for (int kb8 = 0; kb8 < 8; kb8++) {
            if (kb8 < 7) {
                const int kb = (kb8 + 1) * 16;
                ldsm_x4(aN[0], aN[1], aN[2], aN[3],
                        smem_u32(&Qs[(m0w + a_row) * QSTR + kb + a_col]));
                #pragma unroll
                for (int p = 0; p < 4; p++) {
                    int n = p * 16 + b_row;
                    ldsm_x4(bN[2*p][0], bN[2*p][1], bN[2*p+1][0], bN[2*p+1][1],
                            smem_u32(&Ks[n * KSTR + kb + b_col]));
                }
            }
            #pragma unroll
            for (int nf = 0; nf < 8; nf++)
                mma_f16(s[nf], aC, bC[nf]);
            if (kb8 < 7) {
                #pragma unroll
                for (int q = 0; q < 4; q++) aC[q] = aN[q];
                #pragma unroll
                for (int nf = 0; nf < 8; nf++) {
                    bC[nf][0] = bN[nf][0];
                    bC[nf][1] = bN[nf][1];
                }
            }
        }

        // ---- causal mask (diagonal tile only) ----
        if (kt == qblk) {
            int qrow0 = qblk * BQA + m0w + g;
            int col0  = kt * BKA;
            #pragma unroll
            for (int nf = 0; nf < 8; nf++) {
                int c0 = col0 + nf * 8 + tig * 2;
                if (c0     > qrow0)     s[nf][0] = -1e30f;
                if (c0 + 1 > qrow0)     s[nf][1] = -1e30f;
                if (c0     > qrow0 + 8) s[nf][2] = -1e30f;
                if (c0 + 1 > qrow0 + 8) s[nf][3] = -1e30f;
            }
        }

        // ---- online softmax; P packed to half2 in registers ----
        float rm0 = -1e30f, rm1 = -1e30f;
        #pragma unroll
        for (int nf = 0; nf < 8; nf++) {
            rm0 = fmaxf(rm0, fmaxf(s[nf][0], s[nf][1]));
            rm1 = fmaxf(rm1, fmaxf(s[nf][2], s[nf][3]));
        }
        rm0 = fmaxf(rm0, __shfl_xor_sync(0xffffffffu, rm0, 1));
        rm0 = fmaxf(rm0, __shfl_xor_sync(0xffffffffu, rm0, 2));
        rm1 = fmaxf(rm1, __shfl_xor_sync(0xffffffffu, rm1, 1));
        rm1 = fmaxf(rm1, __shfl_xor_sync(0xffffffffu, rm1, 2));
        float mn0 = fmaxf(m0, rm0);
        float mn1 = fmaxf(m1, rm1);

        uint32_t ph[8][2];
        float rs0 = 0.f, rs1 = 0.f;
        #pragma unroll
        for (int nf = 0; nf < 8; nf++) {
            float p00 = __expf((s[nf][0] - mn0) * scale);
            float p01 = __expf((s[nf][1] - mn0) * scale);
            float p10 = __expf((s[nf][2] - mn1) * scale);
            float p11 = __expf((s[nf][3] - mn1) * scale);
            rs0 += p00 + p01;
            rs1 += p10 + p11;
            __half2 h0 = __floats2half2_rn(p00, p01);
            __half2 h1 = __floats2half2_rn(p10, p11);
            ph[nf][0] = *(uint32_t*)&h0;
            ph[nf][1] = *(uint32_t*)&h1;
        }
        rs0 += __shfl_xor_sync(0xffffffffu, rs0, 1);
        rs0 += __shfl_xor_sync(0xffffffffu, rs0, 2);
        rs1 += __shfl_xor_sync(0xffffffffu, rs1, 1);
        rs1 += __shfl_xor_sync(0xffffffffu, rs1, 2);

        float corr0 = __expf((m0 - mn0) * scale);
        float corr1 = __expf((m1 - mn1) * scale);
        l0 = l0 * corr0 + rs0;
        l1 = l1 * corr1 + rs1;
        m0 = mn0; m1 = mn1;
        #pragma unroll
        for (int nf = 0; nf < 16; nf++) {
            o[nf][0] *= corr0; o[nf][1] *= corr0;
            o[nf][2] *= corr1; o[nf][3] *= corr1;
        }

        // ---- O += P V  (pipelined V fragments) ----
        uint32_t vC[4], vN[4];
        ldsm_x4_trans(vC[0], vC[1], vC[2], vC[3],
                      smem_u32(&Vs[a_row * VSTR + a_col]));   // kc=0, np=0
        #pragma unroll
        for (int kc = 0; kc < 4; kc++) {
            const int kb = kc * 16;
            uint32_t a[4] = { ph[2*kc][0], ph[2*kc][1], ph[2*kc+1][0], ph[2*kc+1][1] };
            #pragma unroll
            for (int np = 0; np < 8; np++) {
                // prefetch next V fragment
                if (np < 7) {
                    ldsm_x4_trans(vN[0], vN[1], vN[2], vN[3],
                                  smem_u32(&Vs[(kb + a_row) * VSTR + (np + 1) * 16 + a_col]));
                } else if (kc < 3) {
                    ldsm_x4_trans(vN[0], vN[1], vN[2], vN[3],
                                  smem_u32(&Vs[(kb + 16 + a_row) * VSTR + a_col]));
                }
                uint32_t bb0[2] = { vC[0], vC[1] };
                uint32_t bb1[2] = { vC[2], vC[3] };
                mma_f16(o[2*np],   a, bb0);
                mma_f16(o[2*np+1], a, bb1);
                #pragma unroll
                for (int q = 0; q < 4; q++) vC[q] = vN[q];
            }
        }
    }

    // ---- write O (half, divide by l) ----
    float inv0 = 1.f / l0, inv1 = 1.f / l1;
    int row0 = qblk * BQA + m0w + g;
    __half* ob0 = out + ((size_t)b * SEQ + row0)     * DMODEL + h * HDIM;
    __half* ob1 = out + ((size_t)b * SEQ + row0 + 8) * DMODEL + h * HDIM;
    #pragma unroll
    for (int nf = 0; nf < 16; nf++) {
        *(__half2*)(ob0 + nf * 8 + tig * 2) = __floats2half2_rn(o[nf][0] * inv0, o[nf][1] * inv0);
        *(__half2*)(ob1 + nf * 8 + tig * 2) = __floats2half2_rn(o[nf][2] * inv1, o[nf][3] * inv1);
    }
}

// ---------------------------------------------------------------------------
// Launch
// ---------------------------------------------------------------------------
extern "C" void kernel_launch(void* const* d_in, const int* in_sizes, int n_in,
                              void* d_out, int out_size)
{
    const float* x      = (const float*)d_in[0];
    const float* ln1_g  = (const float*)d_in[1];
    const float* ln1_b  = (const float*)d_in[2];
    const float* w_qkv  = (const float*)d_in[3];
    const float* w_proj = (const float*)d_in[4];
    const float* ln2_g  = (const float*)d_in[5];
    const float* ln2_b  = (const float*)d_in[6];
    const float* w_ff1  = (const float*)d_in[7];
    const float* w_ff2  = (const float*)d_in[8];
    float* out = (float*)d_out;

    float *x1;
    __half *qkvh, *ln1h, *attnh, *ln2h, *ff1h, *wqkvT, *wprojT, *wff1T, *wff2T;
    cudaGetSymbolAddress((void**)&x1,    g_x1);
    cudaGetSymbolAddress((void**)&qkvh,  g_qkvh);
    cudaGetSymbolAddress((void**)&ln1h,  g_ln1h);
    cudaGetSymbolAddress((void**)&attnh, g_attnh);
    cudaGetSymbolAddress((void**)&ln2h,  g_ln2h);
    cudaGetSymbolAddress((void**)&ff1h,  g_ff1h);
    cudaGetSymbolAddress((void**)&wqkvT, g_wqkvT);
    cudaGetSymbolAddress((void**)&wprojT, g_wprojT);
    cudaGetSymbolAddress((void**)&wff1T, g_wff1T);
    cudaGetSymbolAddress((void**)&wff2T, g_wff2T);

    cudaFuncSetAttribute(gemm_h<1>, cudaFuncAttributeMaxDynamicSharedMemorySize, GEMMH_SMEM);
    cudaFuncSetAttribute(gemm_h<2>, cudaFuncAttributeMaxDynamicSharedMemorySize, GEMMH_SMEM);
    cudaFuncSetAttribute(gemm_h<3>, cudaFuncAttributeMaxDynamicSharedMemorySize, GEMMH_SMEM);
    cudaFuncSetAttribute(attn_h,    cudaFuncAttributeMaxDynamicSharedMemorySize, ATTN_SMEM);

    dim3 tb(32, 8);

    // 0. prep: fused weight transposes + ln1
    prep_kernel<<<3584, tb>>>(w_qkv, w_proj, w_ff1, w_ff2,
                              wqkvT, wprojT, wff1T, wff2T,
                              x, ln1_g, ln1_b, ln1h);
    // 2. qkv = ln1 @ w_qkv -> half
    gemm_h<3><<<dim3(1536/128, MROWS/128), 256, GEMMH_SMEM>>>(ln1h, wqkvT, nullptr, qkvh,
                                                              MROWS, 3*DMODEL, DMODEL);
    // 3. attn = causal_flash(qkv) -> half   (BQ=64, balanced heavy-first)
    attn_h<<<dim3(SEQ/BQA, NHEADS, BATCH), 128, ATTN_SMEM>>>(qkvh, attnh);
    // 4. x1 = x + attn @ w_proj -> fp32
    gemm_h<2><<<dim3(512/128, MROWS/128), 256, GEMMH_SMEM>>>(attnh, wprojT, x, x1,
                                                             MROWS, DMODEL, DMODEL);
    // 5. ln2 = LN(x1) -> half
    ln_kernel_h<<<MROWS / 16, tb>>>(x1, ln2_g, ln2_b, ln2h);
    // 6. ff1 = gelu(ln2 @ w_ff1) -> half
    gemm_h<1><<<dim3(DFF/128, MROWS/128), 256, GEMMH_SMEM>>>(ln2h, wff1T, nullptr, ff1h,
                                                             MROWS, DFF, DMODEL);
    // 7. out = x1 + ff1 @ w_ff2 -> fp32
    gemm_h<2><<<dim3(512/128, MROWS/128), 256, GEMMH_SMEM>>>(ff1h, wff2T, x1, out,
                                                             MROWS, DMODEL, DFF);
}

// round 17
// speedup vs baseline: 1.0102x; 1.0102x over previous
#include <cuda_runtime.h>
#include <cuda_fp16.h>
#include <math.h>
#include <stdint.h>

// Problem constants
#define BATCH 4
#define SEQ   2048
#define DMODEL 512
#define NHEADS 4
#define HDIM  128
#define DFF   2048
#define MROWS (BATCH*SEQ)   // 8192

// ---------------------------------------------------------------------------
// Static scratch (no allocation allowed)
// ---------------------------------------------------------------------------
__device__ float  g_x1  [MROWS * DMODEL];       // fp32 residual
__device__ __half g_qkvh [MROWS * 3 * DMODEL];  // half (attention input)
__device__ __half g_ln1h [MROWS * DMODEL];
__device__ __half g_attnh[MROWS * DMODEL];
__device__ __half g_ln2h [MROWS * DMODEL];
__device__ __half g_ff1h [MROWS * DFF];
// transposed half weights [N,K]
__device__ __half g_wqkvT[3 * DMODEL * DMODEL];
__device__ __half g_wprojT[DMODEL * DMODEL];
__device__ __half g_wff1T[DFF * DMODEL];
__device__ __half g_wff2T[DMODEL * DFF];

#define ATT_SCALE 0.08838834764831845f   // 1/sqrt(128)

// ---------------------------------------------------------------------------
// PTX helpers
// ---------------------------------------------------------------------------
__device__ __forceinline__ void mma_f16(float c[4], const uint32_t a[4], const uint32_t b[2]) {
    asm volatile(
        "mma.sync.aligned.m16n8k16.row.col.f32.f16.f16.f32 "
        "{%0,%1,%2,%3}, {%4,%5,%6,%7}, {%8,%9}, {%0,%1,%2,%3};"
        : "+f"(c[0]), "+f"(c[1]), "+f"(c[2]), "+f"(c[3])
        : "r"(a[0]), "r"(a[1]), "r"(a[2]), "r"(a[3]), "r"(b[0]), "r"(b[1]));
}

__device__ __forceinline__ void ldsm_x4(uint32_t& r0, uint32_t& r1, uint32_t& r2, uint32_t& r3,
                                        uint32_t addr) {
    asm volatile("ldmatrix.sync.aligned.m8n8.x4.shared.b16 {%0,%1,%2,%3}, [%4];"
                 : "=r"(r0), "=r"(r1), "=r"(r2), "=r"(r3) : "r"(addr));
}
__device__ __forceinline__ void ldsm_x4_trans(uint32_t& r0, uint32_t& r1, uint32_t& r2, uint32_t& r3,
                                              uint32_t addr) {
    asm volatile("ldmatrix.sync.aligned.m8n8.x4.trans.shared.b16 {%0,%1,%2,%3}, [%4];"
                 : "=r"(r0), "=r"(r1), "=r"(r2), "=r"(r3) : "r"(addr));
}

__device__ __forceinline__ void cp16(uint32_t smem_addr, const void* gmem) {
    asm volatile("cp.async.cg.shared.global [%0], [%1], 16;" :: "r"(smem_addr), "l"(gmem));
}
__device__ __forceinline__ void cp_commit() { asm volatile("cp.async.commit_group;"); }
template <int N>
__device__ __forceinline__ void cp_wait() { asm volatile("cp.async.wait_group %0;" :: "n"(N)); }
__device__ __forceinline__ uint32_t smem_u32(const void* p) {
    return (uint32_t)__cvta_generic_to_shared(p);
}

// ---------------------------------------------------------------------------
// LayerNorm core: one warp handles TWO rows. Block (32,8): 16 rows per block.
// ---------------------------------------------------------------------------
__device__ __forceinline__ void ln_2rows(const float* __restrict__ x,
                                         const float* __restrict__ g,
                                         const float* __restrict__ b,
                                         __half* __restrict__ out,
                                         int row0, int lane)
{
    const float4* xr0 = (const float4*)(x + (size_t)row0 * DMODEL);
    const float4* xr1 = (const float4*)(x + (size_t)(row0 + 1) * DMODEL);
    float4 v0[4], v1[4];
    float sa = 0.f, sa2 = 0.f, sb = 0.f, sb2 = 0.f;
    #pragma unroll
    for (int i = 0; i < 4; i++) {
        v0[i] = xr0[lane + i * 32];
        v1[i] = xr1[lane + i * 32];
    }
    #pragma unroll
    for (int i = 0; i < 4; i++) {
        sa  += v0[i].x + v0[i].y + v0[i].z + v0[i].w;
        sa2 += v0[i].x*v0[i].x + v0[i].y*v0[i].y + v0[i].z*v0[i].z + v0[i].w*v0[i].w;
        sb  += v1[i].x + v1[i].y + v1[i].z + v1[i].w;
        sb2 += v1[i].x*v1[i].x + v1[i].y*v1[i].y + v1[i].z*v1[i].z + v1[i].w*v1[i].w;
    }
    #pragma unroll
    for (int o = 16; o > 0; o >>= 1) {
        sa  += __shfl_xor_sync(0xffffffffu, sa,  o);
        sa2 += __shfl_xor_sync(0xffffffffu, sa2, o);
        sb  += __shfl_xor_sync(0xffffffffu, sb,  o);
        sb2 += __shfl_xor_sync(0xffffffffu, sb2, o);
    }
    float mua  = sa * (1.f / DMODEL);
    float vara = sa2 * (1.f / DMODEL) - mua * mua;
    float inva = rsqrtf(vara + 1e-5f);
    float mub  = sb * (1.f / DMODEL);
    float varb = sb2 * (1.f / DMODEL) - mub * mub;
    float invb = rsqrtf(varb + 1e-5f);

    __half2* o0 = (__half2*)(out + (size_t)row0 * DMODEL);
    __half2* o1 = (__half2*)(out + (size_t)(row0 + 1) * DMODEL);
    const float4* g4 = (const float4*)g;
    const float4* b4 = (const float4*)b;
    #pragma unroll
    for (int i = 0; i < 4; i++) {
        float4 gg = g4[lane + i * 32];
        float4 bb = b4[lane + i * 32];
        float a0 = (v0[i].x - mua) * inva * gg.x + bb.x;
        float a1 = (v0[i].y - mua) * inva * gg.y + bb.y;
        float a2 = (v0[i].z - mua) * inva * gg.z + bb.z;
        float a3 = (v0[i].w - mua) * inva * gg.w + bb.w;
        o0[(lane + i * 32) * 2 + 0] = __floats2half2_rn(a0, a1);
        o0[(lane + i * 32) * 2 + 1] = __floats2half2_rn(a2, a3);
        float c0 = (v1[i].x - mub) * invb * gg.x + bb.x;
        float c1 = (v1[i].y - mub) * invb * gg.y + bb.y;
        float c2 = (v1[i].z - mub) * invb * gg.z + bb.z;
        float c3 = (v1[i].w - mub) * invb * gg.w + bb.w;
        o1[(lane + i * 32) * 2 + 0] = __floats2half2_rn(c0, c1);
        o1[(lane + i * 32) * 2 + 1] = __floats2half2_rn(c2, c3);
    }
}

__global__ void ln_kernel_h(const float* __restrict__ x,
                            const float* __restrict__ g,
                            const float* __restrict__ b,
                            __half* __restrict__ out)
{
    int row0 = blockIdx.x * 16 + threadIdx.y * 2;
    ln_2rows(x, g, b, out, row0, threadIdx.x);
}

// ---------------------------------------------------------------------------
// Prep kernel: fused 4 weight transposes (+fp16 convert) AND ln1.
// ---------------------------------------------------------------------------
__global__ void prep_kernel(const float* __restrict__ w_qkv, const float* __restrict__ w_proj,
                            const float* __restrict__ w_ff1, const float* __restrict__ w_ff2,
                            __half* __restrict__ qkvT, __half* __restrict__ projT,
                            __half* __restrict__ ff1T, __half* __restrict__ ff2T,
                            const float* __restrict__ x, const float* __restrict__ ln1_g,
                            const float* __restrict__ ln1_b, __half* __restrict__ ln1h)
{
    __shared__ float t[32][33];
    int bid = blockIdx.x;
    if (bid >= 3072) {
        int row0 = (bid - 3072) * 16 + threadIdx.y * 2;
        ln_2rows(x, ln1_g, ln1_b, ln1h, row0, threadIdx.x);
        return;
    }

    const float* B; __half* BT; int K, N, bx, by;
    if (bid < 768)        { B = w_qkv;  BT = qkvT;  K = DMODEL; N = 3*DMODEL; bx = bid % 48; by = bid / 48; }
    else if (bid < 1024)  { B = w_proj; BT = projT; K = DMODEL; N = DMODEL;   bid -= 768;  bx = bid % 16; by = bid / 16; }
    else if (bid < 2048)  { B = w_ff1;  BT = ff1T;  K = DMODEL; N = DFF;      bid -= 1024; bx = bid % 64; by = bid / 64; }
    else                  { B = w_ff2;  BT = ff2T;  K = DFF;    N = DMODEL;   bid -= 2048; bx = bid % 16; by = bid / 16; }

    int xcol = bx * 32 + threadIdx.x;
    int y0 = by * 32;
    #pragma unroll
    for (int i = 0; i < 4; i++) {
        int y = y0 + threadIdx.y + i * 8;
        t[threadIdx.y + i * 8][threadIdx.x] = B[(size_t)y * N + xcol];
    }
    __syncthreads();
    int xo  = by * 32 + threadIdx.x;
    int yo0 = bx * 32;
    #pragma unroll
    for (int i = 0; i < 4; i++) {
        int yo = yo0 + threadIdx.y + i * 8;
        BT[(size_t)yo * K + xo] = __float2half_rn(t[threadIdx.x][threadIdx.y + i * 8]);
    }
}

// ---------------------------------------------------------------------------
// fp16 tensor-core GEMM (m16n8k16), BK=64 stages, 3-stage cp.async pipeline,
// ldmatrix frags. Block 128x128x64, 256 threads = 8 warps (4m x 2n).
// EPI: 0 = float out, 1 = GELU half out, 2 = +residual float out, 3 = half out
// ---------------------------------------------------------------------------
#define HS_STR 72                        // halves per row (64 + 8 pad)
#define HT_ELEMS (128 * HS_STR)          // 9216 halves per tile
#define HSTAGE_ELEMS (2 * HT_ELEMS)      // A + B
#define GEMMH_SMEM (3 * HSTAGE_ELEMS * 2)   // 110592 B

__device__ __forceinline__ void load_stage_h(
    uint32_t dstA, uint32_t dstB,
    const __half* Ab, const __half* BTb, int k0, int K, int tid)
{
    #pragma unroll
    for (int t = 0; t < 4; t++) {
        int idx = tid + t * 256;          // 0..1023
        int r = idx >> 3, q = idx & 7;
        cp16(dstA + r * (HS_STR*2) + q * 16, Ab  + (size_t)r * K + k0 + q * 8);
        cp16(dstB + r * (HS_STR*2) + q * 16, BTb + (size_t)r * K + k0 + q * 8);
    }
}

template <int EPI>
__global__ void __launch_bounds__(256, 2)
gemm_h(const __half* __restrict__ A, const __half* __restrict__ BT,
       const float* __restrict__ res, void* __restrict__ Cv,
       int M, int N, int K)
{
    extern __shared__ __half smh[];
    const uint32_t smb = smem_u32(smh);
    uint32_t aAddr[3], bAddr[3];
    #pragma unroll
    for (int s = 0; s < 3; s++) {
        aAddr[s] = smb + s * HSTAGE_ELEMS * 2;
        bAddr[s] = aAddr[s] + HT_ELEMS * 2;
    }

    const int tid  = threadIdx.x;
    const int lane = tid & 31;
    const int wid  = tid >> 5;
    const int wm   = wid >> 1;     // 0..3 (m, x32)
    const int wn   = wid & 1;      // 0..1 (n, x64)

    const int bx = blockIdx.x;
    const int by = blockIdx.y;

    const __half* Ab  = A  + (size_t)(by * 128) * K;
    const __half* BTb = BT + (size_t)(bx * 128) * K;

    float acc[2][8][4];
    #pragma unroll
    for (int mf = 0; mf < 2; mf++)
        #pragma unroll
        for (int nf = 0; nf < 8; nf++)
            #pragma unroll
            for (int r = 0; r < 4; r++) acc[mf][nf][r] = 0.f;

    const int a_row = (lane & 15);
    const int a_col = (lane >> 4) << 3;
    const int b_row = (lane & 7) + ((lane >> 4) << 3);
    const int b_col = (lane & 8) ? 8 : 0;

    const int nt = K >> 6;   // BK=64 chunks
    load_stage_h(aAddr[0], bAddr[0], Ab, BTb, 0, K, tid);
    cp_commit();
    if (nt > 1) {
        load_stage_h(aAddr[1], bAddr[1], Ab, BTb, 64, K, tid);
        cp_commit();
    }

    for (int kt = 0; kt < nt; kt++) {
        const int cur = kt % 3;
        if (kt + 1 < nt) cp_wait<1>(); else cp_wait<0>();
        __syncthreads();

        if (kt + 2 < nt) {
            const int nxt = (kt + 2) % 3;
            load_stage_h(aAddr[nxt], bAddr[nxt], Ab, BTb, (kt + 2) * 64, K, tid);
            cp_commit();
        }

        const uint32_t Asc = aAddr[cur];
        const uint32_t Bsc = bAddr[cur];

        #pragma unroll
        for (int ks = 0; ks < 4; ks++) {
            const int kb = ks * 16;
            uint32_t af[2][4], bf[8][2];
            #pragma unroll
            for (int mf = 0; mf < 2; mf++) {
                int r = wm * 32 + mf * 16 + a_row;
                ldsm_x4(af[mf][0], af[mf][1], af[mf][2], af[mf][3],
                        Asc + (r * HS_STR + kb + a_col) * 2);
            }
            #pragma unroll
            for (int p = 0; p < 4; p++) {
                int n = wn * 64 + p * 16 + b_row;
                ldsm_x4(bf[2*p][0], bf[2*p][1], bf[2*p+1][0], bf[2*p+1][1],
                        Bsc + (n * HS_STR + kb + b_col) * 2);
            }
            #pragma unroll
            for (int mf = 0; mf < 2; mf++)
                #pragma unroll
                for (int nf = 0; nf < 8; nf++)
                    mma_f16(acc[mf][nf], af[mf], bf[nf]);
        }
    }

    // epilogue
    const int g   = lane >> 2;
    const int tig = lane & 3;
    #pragma unroll
    for (int mf = 0; mf < 2; mf++) {
        #pragma unroll
        for (int i2 = 0; i2 < 2; i2++) {
            int row = by * 128 + wm * 32 + mf * 16 + g + i2 * 8;
            #pragma unroll
            for (int nf = 0; nf < 8; nf++) {
                int col = bx * 128 + wn * 64 + nf * 8 + tig * 2;
                float v0 = acc[mf][nf][i2 * 2 + 0];
                float v1 = acc[mf][nf][i2 * 2 + 1];
                size_t off = (size_t)row * N + col;
                if (EPI == 1) {
                    v0 = 0.5f * v0 * (1.f + erff(v0 * 0.70710678118654752f));
                    v1 = 0.5f * v1 * (1.f + erff(v1 * 0.70710678118654752f));
                    *(__half2*)((__half*)Cv + off) = __floats2half2_rn(v0, v1);
                } else if (EPI == 2) {
                    float2 r = *(const float2*)(res + off);
                    *(float2*)((float*)Cv + off) = make_float2(v0 + r.x, v1 + r.y);
                } else if (EPI == 3) {
                    *(__half2*)((__half*)Cv + off) = __floats2half2_rn(v0, v1);
                } else {
                    *(float2*)((float*)Cv + off) = make_float2(v0, v1);
                }
            }
        }
    }
}

// ---------------------------------------------------------------------------
// fp16 flash attention v6: BQ=64 (4 warps x 16 q-rows), Q-fragments resident
// in registers (loaded once), register-resident P, 2-stage cp.async K/V
// pipeline, half output. 512 CTAs heavy-first.
// Smem: Q[64][136] + 2 x (K+V)[64][136] = 87040 B. 2 CTAs/SM (256-reg budget).
// ---------------------------------------------------------------------------
#define BQA 64
#define BKA 64
#define QSTR 136   // halves
#define KSTR 136
#define VSTR 136
#define KV_STAGE_ELEMS (BKA * KSTR + BKA * VSTR)       // 17408 halves
#define ATTN_SMEM ((BQA*QSTR + 2*KV_STAGE_ELEMS) * 2)  // 87040 B

__global__ void __launch_bounds__(128, 2)
attn_h(const __half* __restrict__ qkv, __half* __restrict__ out)
{
    extern __shared__ __align__(16) __half smah[];
    __half* Qs = smah;                               // [64][136]
    uint32_t kAddr[2], vAddr[2];
    {
        uint32_t kv0 = smem_u32(Qs + BQA * QSTR);
        kAddr[0] = kv0;
        vAddr[0] = kv0 + BKA * KSTR * 2;
        kAddr[1] = kv0 + KV_STAGE_ELEMS * 2;
        vAddr[1] = kAddr[1] + BKA * KSTR * 2;
    }
    __half* KsBase = Qs + BQA * QSTR;
    const uint32_t qAddr = smem_u32(Qs);

    const int qblk = (SEQ / BQA - 1) - blockIdx.x;   // heavy blocks first
    const int h  = blockIdx.y;
    const int b  = blockIdx.z;
    const int tid  = threadIdx.x;
    const int lane = tid & 31;
    const int wid  = tid >> 5;
    const int g    = lane >> 2;
    const int tig  = lane & 3;
    const int m0w  = wid * 16;

    const size_t rstride = 3 * DMODEL;  // halves
    const float scale = ATT_SCALE;

    const int a_row = (lane & 15);
    const int a_col = (lane >> 4) << 3;
    const int b_row = (lane & 7) + ((lane >> 4) << 3);
    const int b_col = (lane & 8) ? 8 : 0;

    const __half* kvbase = qkv + (size_t)b * SEQ * rstride + h * HDIM + DMODEL;

    // ---- prologue: Q tile + K/V tile 0 via cp.async (one group) ----
    {
        const __half* qbase = qkv + ((size_t)b * SEQ + qblk * BQA) * rstride + h * HDIM;
        #pragma unroll
        for (int t = 0; t < 8; t++) {
            int idx = tid + t * 128;
            int row = idx >> 4, q8 = idx & 15;
            cp16(qAddr + (row * QSTR + q8 * 8) * 2, qbase + (size_t)row * rstride + q8 * 8);
        }
        #pragma unroll
        for (int t = 0; t < 8; t++) {
            int idx = tid + t * 128;
            int row = idx >> 4, q8 = idx & 15;
            cp16(kAddr[0] + (row * KSTR + q8 * 8) * 2, kvbase + (size_t)row * rstride + q8 * 8);
            cp16(vAddr[0] + (row * VSTR + q8 * 8) * 2, kvbase + DMODEL + (size_t)row * rstride + q8 * 8);
        }
        cp_commit();
    }

    float o[16][4];
    #pragma unroll
    for (int nf = 0; nf < 16; nf++)
        #pragma unroll
        for (int r = 0; r < 4; r++) o[nf][r] = 0.f;
    float m0 = -1e30f, m1 = -1e30f, l0 = 0.f, l1 = 0.f;

    uint32_t qf[8][4];   // Q fragments, resident across the whole K loop

    const int ntiles = qblk + 1;

    for (int kt = 0; kt < ntiles; kt++) {
        const int cur = kt & 1;
        __syncthreads();

        if (kt + 1 < ntiles) {
            const int nxt = 1 - cur;
            const __half* kbn = kvbase + (size_t)(kt + 1) * BKA * rstride;
            #pragma unroll
            for (int t = 0; t < 8; t++) {
                int idx = tid + t * 128;
                int row = idx >> 4, q8 = idx & 15;
                cp16(kAddr[nxt] + (row * KSTR + q8 * 8) * 2, kbn + (size_t)row * rstride + q8 * 8);
                cp16(vAddr[nxt] + (row * VSTR + q8 * 8) * 2, kbn + DMODEL + (size_t)row * rstride + q8 * 8);
            }
            cp_commit();
            cp_wait<1>();
        } else {
            cp_wait<0>();
        }
        __syncthreads();

        // Load Q fragments once (stage 0 made Q visible)
        if (kt == 0) {
            #pragma unroll
            for (int kb8 = 0; kb8 < 8; kb8++)
                ldsm_x4(qf[kb8][0], qf[kb8][1], qf[kb8][2], qf[kb8][3],
                        smem_u32(&Qs[(m0w + a_row) * QSTR + kb8 * 16 + a_col]));
        }

        const __half* Ks = KsBase + cur * KV_STAGE_ELEMS;
        const __half* Vs = Ks + BKA * KSTR;

        // ---- S = Q K^T (Q from registers) ----
        float s[8][4];
        #pragma unroll
        for (int nf = 0; nf < 8; nf++)
            #pragma unroll
            for (int r = 0; r < 4; r++) s[nf][r] = 0.f;

        #pragma unroll
        for (int kb8 = 0; kb8 < 8; kb8++) {
            const int kb = kb8 * 16;
            uint32_t bf[8][2];
            #pragma unroll
            for (int p = 0; p < 4; p++) {
                int n = p * 16 + b_row;
                ldsm_x4(bf[2*p][0], bf[2*p][1], bf[2*p+1][0], bf[2*p+1][1],
                        smem_u32(&Ks[n * KSTR + kb + b_col]));
            }
            #pragma unroll
            for (int nf = 0; nf < 8; nf++)
                mma_f16(s[nf], qf[kb8], bf[nf]);
        }

        // ---- causal mask (diagonal tile only) ----
        if (kt == qblk) {
            int qrow0 = qblk * BQA + m0w + g;
            int col0  = kt * BKA;
            #pragma unroll
            for (int nf = 0; nf < 8; nf++) {
                int c0 = col0 + nf * 8 + tig * 2;
                if (c0     > qrow0)     s[nf][0] = -1e30f;
                if (c0 + 1 > qrow0)     s[nf][1] = -1e30f;
                if (c0     > qrow0 + 8) s[nf][2] = -1e30f;
                if (c0 + 1 > qrow0 + 8) s[nf][3] = -1e30f;
            }
        }

        // ---- online softmax; P packed to half2 in registers ----
        float rm0 = -1e30f, rm1 = -1e30f;
        #pragma unroll
        for (int nf = 0; nf < 8; nf++) {
            rm0 = fmaxf(rm0, fmaxf(s[nf][0], s[nf][1]));
            rm1 = fmaxf(rm1, fmaxf(s[nf][2], s[nf][3]));
        }
        rm0 = fmaxf(rm0, __shfl_xor_sync(0xffffffffu, rm0, 1));
        rm0 = fmaxf(rm0, __shfl_xor_sync(0xffffffffu, rm0, 2));
        rm1 = fmaxf(rm1, __shfl_xor_sync(0xffffffffu, rm1, 1));
        rm1 = fmaxf(rm1, __shfl_xor_sync(0xffffffffu, rm1, 2));
        float mn0 = fmaxf(m0, rm0);
        float mn1 = fmaxf(m1, rm1);

        uint32_t ph[8][2];
        float rs0 = 0.f, rs1 = 0.f;
        #pragma unroll
        for (int nf = 0; nf < 8; nf++) {
            float p00 = __expf((s[nf][0] - mn0) * scale);
            float p01 = __expf((s[nf][1] - mn0) * scale);
            float p10 = __expf((s[nf][2] - mn1) * scale);
            float p11 = __expf((s[nf][3] - mn1) * scale);
            rs0 += p00 + p01;
            rs1 += p10 + p11;
            __half2 h0 = __floats2half2_rn(p00, p01);
            __half2 h1 = __floats2half2_rn(p10, p11);
            ph[nf][0] = *(uint32_t*)&h0;
            ph[nf][1] = *(uint32_t*)&h1;
        }
        rs0 += __shfl_xor_sync(0xffffffffu, rs0, 1);
        rs0 += __shfl_xor_sync(0xffffffffu, rs0, 2);
        rs1 += __shfl_xor_sync(0xffffffffu, rs1, 1);
        rs1 += __shfl_xor_sync(0xffffffffu, rs1, 2);

        float corr0 = __expf((m0 - mn0) * scale);
        float corr1 = __expf((m1 - mn1) * scale);
        l0 = l0 * corr0 + rs0;
        l1 = l1 * corr1 + rs1;
        m0 = mn0; m1 = mn1;
        #pragma unroll
        for (int nf = 0; nf < 16; nf++) {
            o[nf][0] *= corr0; o[nf][1] *= corr0;
            o[nf][2] *= corr1; o[nf][3] *= corr1;
        }

        // ---- O += P V ----
        #pragma unroll
        for (int kc = 0; kc < 4; kc++) {
            const int kb = kc * 16;
            uint32_t a[4] = { ph[2*kc][0], ph[2*kc][1], ph[2*kc+1][0], ph[2*kc+1][1] };
            #pragma unroll
            for (int np = 0; np < 8; np++) {
                uint32_t b0, b1, b2, b3;
                ldsm_x4_trans(b0, b1, b2, b3,
                              smem_u32(&Vs[(kb + a_row) * VSTR + np * 16 + a_col]));
                uint32_t bb0[2] = { b0, b1 };
                uint32_t bb1[2] = { b2, b3 };
                mma_f16(o[2*np],   a, bb0);
                mma_f16(o[2*np+1], a, bb1);
            }
        }
    }

    // ---- write O (half, divide by l) ----
    float inv0 = 1.f / l0, inv1 = 1.f / l1;
    int row0 = qblk * BQA + m0w + g;
    __half* ob0 = out + ((size_t)b * SEQ + row0)     * DMODEL + h * HDIM;
    __half* ob1 = out + ((size_t)b * SEQ + row0 + 8) * DMODEL + h * HDIM;
    #pragma unroll
    for (int nf = 0; nf < 16; nf++) {
        *(__half2*)(ob0 + nf * 8 + tig * 2) = __floats2half2_rn(o[nf][0] * inv0, o[nf][1] * inv0);
        *(__half2*)(ob1 + nf * 8 + tig * 2) = __floats2half2_rn(o[nf][2] * inv1, o[nf][3] * inv1);
    }
}

// ---------------------------------------------------------------------------
// Launch
// ---------------------------------------------------------------------------
extern "C" void kernel_launch(void* const* d_in, const int* in_sizes, int n_in,
                              void* d_out, int out_size)
{
    const float* x      = (const float*)d_in[0];
    const float* ln1_g  = (const float*)d_in[1];
    const float* ln1_b  = (const float*)d_in[2];
    const float* w_qkv  = (const float*)d_in[3];
    const float* w_proj = (const float*)d_in[4];
    const float* ln2_g  = (const float*)d_in[5];
    const float* ln2_b  = (const float*)d_in[6];
    const float* w_ff1  = (const float*)d_in[7];
    const float* w_ff2  = (const float*)d_in[8];
    float* out = (float*)d_out;

    float *x1;
    __half *qkvh, *ln1h, *attnh, *ln2h, *ff1h, *wqkvT, *wprojT, *wff1T, *wff2T;
    cudaGetSymbolAddress((void**)&x1,    g_x1);
    cudaGetSymbolAddress((void**)&qkvh,  g_qkvh);
    cudaGetSymbolAddress((void**)&ln1h,  g_ln1h);
    cudaGetSymbolAddress((void**)&attnh, g_attnh);
    cudaGetSymbolAddress((void**)&ln2h,  g_ln2h);
    cudaGetSymbolAddress((void**)&ff1h,  g_ff1h);
    cudaGetSymbolAddress((void**)&wqkvT, g_wqkvT);
    cudaGetSymbolAddress((void**)&wprojT, g_wprojT);
    cudaGetSymbolAddress((void**)&wff1T, g_wff1T);
    cudaGetSymbolAddress((void**)&wff2T, g_wff2T);

    cudaFuncSetAttribute(gemm_h<1>, cudaFuncAttributeMaxDynamicSharedMemorySize, GEMMH_SMEM);
    cudaFuncSetAttribute(gemm_h<2>, cudaFuncAttributeMaxDynamicSharedMemorySize, GEMMH_SMEM);
    cudaFuncSetAttribute(gemm_h<3>, cudaFuncAttributeMaxDynamicSharedMemorySize, GEMMH_SMEM);
    cudaFuncSetAttribute(attn_h,    cudaFuncAttributeMaxDynamicSharedMemorySize, ATTN_SMEM);

    dim3 tb(32, 8);

    // 0. prep: fused weight transposes + ln1
    prep_kernel<<<3584, tb>>>(w_qkv, w_proj, w_ff1, w_ff2,
                              wqkvT, wprojT, wff1T, wff2T,
                              x, ln1_g, ln1_b, ln1h);
    // 2. qkv = ln1 @ w_qkv -> half
    gemm_h<3><<<dim3(1536/128, MROWS/128), 256, GEMMH_SMEM>>>(ln1h, wqkvT, nullptr, qkvh,
                                                              MROWS, 3*DMODEL, DMODEL);
    // 3. attn = causal_flash(qkv) -> half   (BQ=64, balanced heavy-first)
    attn_h<<<dim3(SEQ/BQA, NHEADS, BATCH), 128, ATTN_SMEM>>>(qkvh, attnh);
    // 4. x1 = x + attn @ w_proj -> fp32
    gemm_h<2><<<dim3(512/128, MROWS/128), 256, GEMMH_SMEM>>>(attnh, wprojT, x, x1,
                                                             MROWS, DMODEL, DMODEL);
    // 5. ln2 = LN(x1) -> half
    ln_kernel_h<<<MROWS / 16, tb>>>(x1, ln2_g, ln2_b, ln2h);
    // 6. ff1 = gelu(ln2 @ w_ff1) -> half
    gemm_h<1><<<dim3(DFF/128, MROWS/128), 256, GEMMH_SMEM>>>(ln2h, wff1T, nullptr, ff1h,
                                                             MROWS, DFF, DMODEL);
    // 7. out = x1 + ff1 @ w_ff2 -> fp32
    gemm_h<2><<<dim3(512/128, MROWS/128), 256, GEMMH_SMEM>>>(ff1h, wff2T, x1, out,
                                                             MROWS, DMODEL, DFF);
}